// round 1
// baseline (speedup 1.0000x reference)
#include <cuda_runtime.h>
#include <cstdint>
#include <math.h>

// Problem constants (fixed by the reference)
#define N_GLOB 256
#define M_GLOB 1024
#define D_GLOB 512
#define H_GLOB 512

// Tiling
#define N_SUB   16     // e-rows per CTA
#define M_SUB   8      // s-rows per CTA
#define P_TILE  128    // pairs per CTA  = N_SUB * M_SUB
#define H_TILE  128    // H columns per block
#define K_TILE  32     // K (D) per mainloop step

// SMEM pads chosen so fragment loads hit banks (4*row + col) & 31 -> conflict-free
#define AS_PAD  36
#define BS_PAD  132

__device__ __forceinline__ uint32_t f2tf32(float f) {
    uint32_t r;
    asm("cvt.rna.tf32.f32 %0, %1;" : "=r"(r) : "f"(f));
    return r;
}

__global__ void __launch_bounds__(256, 2)
support_layer_kernel(const float* __restrict__ E,   // [N, D]
                     const float* __restrict__ S,   // [M, D]
                     const float* __restrict__ W1,  // [D, H]
                     const float* __restrict__ B1,  // [H]
                     const float* __restrict__ W2,  // [H, 1]
                     const float* __restrict__ B2,  // [1]
                     float* __restrict__ out)       // [N, M]
{
    __shared__ float As[P_TILE][AS_PAD];   // |e - s| tile, tf32-rounded
    __shared__ float Bs[K_TILE][BS_PAD];   // W1 tile, tf32-rounded
    __shared__ float partial[P_TILE];

    const int tid  = threadIdx.x;
    const int wid  = tid >> 5;
    const int lane = tid & 31;
    const int warp_m = wid & 1;   // 2 warps along pairs (64 rows each)
    const int warp_n = wid >> 1;  // 4 warps along H   (32 cols each)

    const int n0 = blockIdx.y * N_SUB;
    const int m0 = blockIdx.x * M_SUB;

    float psum[8];
    #pragma unroll
    for (int i = 0; i < 8; ++i) psum[i] = 0.f;
    if (tid < P_TILE) partial[tid] = 0.f;

    float acc[4][4][4];  // [m_tile][n_tile][frag]

    for (int hb = 0; hb < H_GLOB / H_TILE; ++hb) {
        const int j0 = hb * H_TILE;
        #pragma unroll
        for (int mt = 0; mt < 4; ++mt)
            #pragma unroll
            for (int nt = 0; nt < 4; ++nt)
                #pragma unroll
                for (int r = 0; r < 4; ++r) acc[mt][nt][r] = 0.f;

        for (int k0 = 0; k0 < D_GLOB; k0 += K_TILE) {
            __syncthreads();
            // Build A tile: As[p][k] = tf32(|E[n0 + p/8, k0+k] - S[m0 + p%8, k0+k]|)
            #pragma unroll
            for (int i = tid; i < P_TILE * K_TILE; i += 256) {
                const int p = i >> 5, k = i & 31;
                const float e = E[(n0 + (p >> 3)) * D_GLOB + k0 + k];
                const float s = S[(m0 + (p & 7))  * D_GLOB + k0 + k];
                As[p][k] = __uint_as_float(f2tf32(fabsf(e - s)));
            }
            // Load W1 tile: Bs[k][n] = tf32(W1[k0+k, j0+n])
            #pragma unroll
            for (int i = tid; i < K_TILE * H_TILE; i += 256) {
                const int k = i >> 7, n = i & 127;
                Bs[k][n] = __uint_as_float(f2tf32(W1[(k0 + k) * H_GLOB + j0 + n]));
            }
            __syncthreads();

            #pragma unroll
            for (int kt = 0; kt < 4; ++kt) {   // 4 x k=8 per K_TILE
                uint32_t a[4][4], b[4][2];
                const int ar = warp_m * 64 + (lane >> 2);
                const int ac = kt * 8 + (lane & 3);
                #pragma unroll
                for (int mt = 0; mt < 4; ++mt) {
                    a[mt][0] = __float_as_uint(As[ar + mt * 16    ][ac]);
                    a[mt][1] = __float_as_uint(As[ar + mt * 16 + 8][ac]);
                    a[mt][2] = __float_as_uint(As[ar + mt * 16    ][ac + 4]);
                    a[mt][3] = __float_as_uint(As[ar + mt * 16 + 8][ac + 4]);
                }
                const int bk = kt * 8 + (lane & 3);
                const int bn = warp_n * 32 + (lane >> 2);
                #pragma unroll
                for (int nt = 0; nt < 4; ++nt) {
                    b[nt][0] = __float_as_uint(Bs[bk    ][bn + nt * 8]);
                    b[nt][1] = __float_as_uint(Bs[bk + 4][bn + nt * 8]);
                }
                #pragma unroll
                for (int mt = 0; mt < 4; ++mt)
                    #pragma unroll
                    for (int nt = 0; nt < 4; ++nt) {
                        asm volatile(
                            "mma.sync.aligned.m16n8k8.row.col.f32.tf32.tf32.f32 "
                            "{%0,%1,%2,%3}, {%4,%5,%6,%7}, {%8,%9}, {%0,%1,%2,%3};\n"
                            : "+f"(acc[mt][nt][0]), "+f"(acc[mt][nt][1]),
                              "+f"(acc[mt][nt][2]), "+f"(acc[mt][nt][3])
                            : "r"(a[mt][0]), "r"(a[mt][1]), "r"(a[mt][2]), "r"(a[mt][3]),
                              "r"(b[nt][0]), "r"(b[nt][1]));
                    }
            }
        }

        // Epilogue for this H-block: relu(+b1) * W2, reduce over j into per-pair psum
        #pragma unroll
        for (int mt = 0; mt < 4; ++mt) {
            #pragma unroll
            for (int nt = 0; nt < 4; ++nt) {
                const int jg = j0 + warp_n * 32 + nt * 8 + (lane & 3) * 2;
                const float b1a = B1[jg],   b1b = B1[jg + 1];
                const float w2a = W2[jg],   w2b = W2[jg + 1];
                // frag mapping: d0=(p0,jg) d1=(p0,jg+1) d2=(p0+8,jg) d3=(p0+8,jg+1)
                const float h0 = fmaxf(acc[mt][nt][0] + b1a, 0.f);
                const float h1 = fmaxf(acc[mt][nt][1] + b1b, 0.f);
                const float h2 = fmaxf(acc[mt][nt][2] + b1a, 0.f);
                const float h3 = fmaxf(acc[mt][nt][3] + b1b, 0.f);
                psum[mt * 2 + 0] += h0 * w2a + h1 * w2b;
                psum[mt * 2 + 1] += h2 * w2a + h3 * w2b;
            }
        }
    }

    __syncthreads();
    const int prow = warp_m * 64 + (lane >> 2);
    #pragma unroll
    for (int mt = 0; mt < 4; ++mt) {
        atomicAdd(&partial[prow + mt * 16    ], psum[mt * 2 + 0]);
        atomicAdd(&partial[prow + mt * 16 + 8], psum[mt * 2 + 1]);
    }
    __syncthreads();

    if (tid < P_TILE) {
        const float logit = partial[tid] + B2[0];
        const int n = n0 + (tid >> 3);
        const int m = m0 + (tid & 7);
        out[n * M_GLOB + m] = 1.f / (1.f + expf(-logit));
    }
}

extern "C" void kernel_launch(void* const* d_in, const int* in_sizes, int n_in,
                              void* d_out, int out_size)
{
    const float* E  = (const float*)d_in[0];
    const float* S  = (const float*)d_in[1];
    const float* W1 = (const float*)d_in[2];
    const float* B1 = (const float*)d_in[3];
    const float* W2 = (const float*)d_in[4];
    const float* B2 = (const float*)d_in[5];
    float* out = (float*)d_out;

    dim3 grid(M_GLOB / M_SUB, N_GLOB / N_SUB);  // (128, 16) = 2048 CTAs
    support_layer_kernel<<<grid, 256>>>(E, S, W1, B1, W2, B2, out);
}